// round 1
// baseline (speedup 1.0000x reference)
#include <cuda_runtime.h>
#include <cuda_bf16.h>

// MVDR beamformer: B=2, C=128, NS=1024, NZ=256, NX=128, L_SUB=16, M=113.
// One pixel per 16-lane group (2 pixels per warp). G (=M*R) built via the
// lag recurrence G[l][k] = G[l-1][k-1] - xf[l-1]xf[k-1] + xf[112+l]xf[112+k],
// row-distributed (lane i holds row i). Cholesky + solves fully unrolled
// with width-16 shuffles, no divisions (rsqrt+Newton gives 1/L[k][k]).

#define FULLM 0xffffffffu

constexpr int Bn = 2, Cn = 128, NSn = 1024, NZn = 256, NXn = 128;
constexpr int PIX = Bn * NZn * NXn;   // 65536
constexpr int PPB = 16;               // pixels per 256-thread block
constexpr float DLc = 0.05f;

__device__ __forceinline__ float shf(float v, int s)  { return __shfl_sync(FULLM, v, s, 16); }
__device__ __forceinline__ float shfu(float v)        { return __shfl_up_sync(FULLM, v, 1, 16); }
__device__ __forceinline__ float shfx(float v, int m) { return __shfl_xor_sync(FULLM, v, m, 16); }

__global__ __launch_bounds__(256) void mvdr_kernel(
    const float* __restrict__ rf,   // [B, C, NS]
    const float* __restrict__ t0,   // [B]
    const float* __restrict__ dtx,  // [B, NZ, NX]
    const float* __restrict__ drx,  // [C, NZ, NX]
    const float* __restrict__ fsp,  // [1]
    const float* __restrict__ c0p,  // [1]
    float* __restrict__ out)        // [B, NZ, NX]
{
    // stride 144: 144 mod 32 == 16 -> the two 16-lane groups of a warp hit
    // disjoint bank halves on every access pattern used below.
    __shared__ float xf[PPB][144];

    const int tid  = threadIdx.x;
    const int grp  = tid >> 4;
    const int lane = tid & 15;
    const int p    = blockIdx.x * PPB + grp;        // pixel id, order (b,z,x)
    const int b    = p >> 15;                       // / (NZ*NX = 32768)
    const int rem  = p & 32767;                     // z*NX + x

    const float fs   = __ldg(fsp);
    const float ic0  = 1.0f / __ldg(c0p);
    const float t0v  = __ldg(t0 + b);
    const float dtxv = __ldg(dtx + b * 32768 + rem);
    const float* rfb = rf + b * (Cn * NSn);
    float* X = xf[grp];

    // ---- delay-and-interpolate: 8 channels per lane ----
    #pragma unroll
    for (int j = 0; j < 8; j++) {
        int c = lane + 16 * j;
        float pos = fs * ((dtxv + __ldg(drx + c * 32768 + rem)) * ic0 + t0v);
        pos = fminf(fmaxf(pos, 0.0f), 1023.0f);
        float fi = floorf(pos);
        int i0 = (int)fi;
        int i1 = min(i0 + 1, NSn - 1);
        float fr = pos - fi;
        const float* rc = rfb + c * NSn;
        float v0 = __ldg(rc + i0), v1 = __ldg(rc + i1);
        X[c] = fmaf(fr, v1 - v0, v0);
    }
    __syncwarp();

    // ---- row 0 of G and the lag-sum xs (fused) ----
    float g0 = 0.0f, xs = 0.0f;
    #pragma unroll 4
    for (int m = 0; m < 113; m++) {
        float vm = X[m];          // broadcast within group
        float vk = X[m + lane];   // consecutive, conflict-free
        g0 = fmaf(vm, vk, g0);
        xs += vk;
    }
    float xlo = X[lane];
    float xhi = X[112 + lane];

    // ---- remaining rows via the lag recurrence; deposit column l ----
    float g[16];
    float cur = g0;
    g[0] = cur;
    float tr = shf(cur, 0);
    #pragma unroll
    for (int l = 1; l < 16; l++) {
        float a   = shfu(cur);        // G[l-1][k-1]
        float xk1 = shfu(xlo);        // xf[k-1]
        float xl1 = shf(xlo, l - 1);  // xf[l-1]   (broadcast)
        float xhl = shf(xhi, l);      // xf[112+l] (broadcast)
        float nxt = fmaf(xhl, xhi, fmaf(-xl1, xk1, a));
        float bnd = shf(g0, l);       // G[l][0] = G[0][l]
        nxt = (lane == 0) ? bnd : nxt;
        cur = nxt;
        g[l] = cur;                   // lane k: g[l] = G[l][k] = G[k][l]
        tr += shf(cur, l);
    }

    // ---- diagonal loading: Ghat = G + (DL/16)*tr(G) * I ----
    float d = (DLc / 16.0f) * tr;
    #pragma unroll
    for (int j = 0; j < 16; j++) g[j] += (lane == j) ? d : 0.0f;

    // ---- Cholesky, row-distributed, right-looking ----
    float lmat[16], linv[16];
    #pragma unroll
    for (int k = 0; k < 16; k++) {
        float diag = shf(g[k], k);
        float inv = rsqrtf(diag);
        inv = inv * fmaf(-0.5f * diag * inv, inv, 1.5f);  // Newton refine
        float lik = g[k] * inv;       // lane i>=k: L[i][k]; lane k: sqrt(diag)
        lmat[k] = lik;
        linv[k] = inv;                // uniform across lanes = 1/L[k][k]
        #pragma unroll
        for (int j = k + 1; j < 16; j++) {
            float ljk = shf(lik, j);
            g[j] = fmaf(-lik, ljk, g[j]);
        }
    }

    // ---- forward solve L y = 1 ----
    float s = 0.0f, yown = 0.0f;
    #pragma unroll
    for (int k = 0; k < 16; k++) {
        float t  = (1.0f - s) * linv[k];  // meaningful on lane k
        float yk = shf(t, k);
        yown = (lane == k) ? yk : yown;
        s = fmaf(lmat[k], yk, s);
    }

    // ---- backward solve L^T u = y ----
    float uown = 0.0f;
    #pragma unroll
    for (int j = 15; j >= 0; j--) {
        float part = (lane > j) ? lmat[j] * uown : 0.0f;
        part += shfx(part, 8); part += shfx(part, 4);
        part += shfx(part, 2); part += shfx(part, 1);
        float t  = (yown - part) * linv[j];  // meaningful on lane j
        float uj = shf(t, j);
        uown = (lane == j) ? uj : uown;
    }

    // ---- y = <u, xs> / (M * sum(u) + 1e-10)  (1/M scaling cancels) ----
    float dot = uown * xs;
    float sv  = uown;
    #pragma unroll
    for (int m = 8; m; m >>= 1) { dot += shfx(dot, m); sv += shfx(sv, m); }
    float y = dot / fmaf(113.0f, sv, 1e-10f);
    if (lane == 0) out[p] = y;
}

extern "C" void kernel_launch(void* const* d_in, const int* in_sizes, int n_in,
                              void* d_out, int out_size)
{
    const float* rf  = (const float*)d_in[0];
    const float* t0  = (const float*)d_in[1];
    const float* dtx = (const float*)d_in[2];
    const float* drx = (const float*)d_in[3];
    const float* fs  = (const float*)d_in[4];
    // d_in[5] = f0 (unused), d_in[7] = apod (unused, all ones in reference path)
    const float* c0  = (const float*)d_in[6];
    mvdr_kernel<<<PIX / PPB, 256>>>(rf, t0, dtx, drx, fs, c0, (float*)d_out);
}

// round 2
// speedup vs baseline: 1.5994x; 1.5994x over previous
#include <cuda_runtime.h>
#include <cuda_bf16.h>

// MVDR beamformer: B=2, C=128, NS=1024, NZ=256, NX=128, L_SUB=16, M=113.
// R2: zero shared memory. Aligned signal X[0..127] lives in 8 regs/lane
// (w[q] = X[lane+16q]); the correlation row-0 loop reads the sliding window
// via width-16 shuffles instead of LDS, taking all LDS traffic off the
// saturated L1tex pipe (91% in R1). Everything else register/shuffle-resident.

#define FULLM 0xffffffffu

constexpr int Bn = 2, Cn = 128, NSn = 1024, NZn = 256, NXn = 128;
constexpr int PIX = Bn * NZn * NXn;   // 65536
constexpr int PPB = 16;               // pixels per 256-thread block
constexpr float DLc = 0.05f;

__device__ __forceinline__ float shf(float v, int s)  { return __shfl_sync(FULLM, v, s, 16); }
__device__ __forceinline__ float shfu(float v)        { return __shfl_up_sync(FULLM, v, 1, 16); }
__device__ __forceinline__ float shfx(float v, int m) { return __shfl_xor_sync(FULLM, v, m, 16); }

__global__ __launch_bounds__(256) void mvdr_kernel(
    const float* __restrict__ rf,   // [B, C, NS]
    const float* __restrict__ t0,   // [B]
    const float* __restrict__ dtx,  // [B, NZ, NX]
    const float* __restrict__ drx,  // [C, NZ, NX]
    const float* __restrict__ fsp,  // [1]
    const float* __restrict__ c0p,  // [1]
    float* __restrict__ out)        // [B, NZ, NX]
{
    const int tid  = threadIdx.x;
    const int grp  = tid >> 4;
    const int lane = tid & 15;
    const int p    = blockIdx.x * PPB + grp;        // pixel id, order (b,z,x)
    const int b    = p >> 15;                       // / (NZ*NX = 32768)
    const int rem  = p & 32767;                     // z*NX + x

    const float fs   = __ldg(fsp);
    const float ic0  = 1.0f / __ldg(c0p);
    const float t0v  = __ldg(t0 + b);
    const float dtxv = __ldg(dtx + b * 32768 + rem);
    const float* rfb = rf + b * (Cn * NSn);

    // ---- delay-and-interpolate straight into registers: w[q] = X[lane+16q] ----
    float w[8];
    #pragma unroll
    for (int q = 0; q < 8; q++) {
        int c = lane + 16 * q;
        float pos = fs * ((dtxv + __ldg(drx + c * 32768 + rem)) * ic0 + t0v);
        pos = fminf(fmaxf(pos, 0.0f), 1023.0f);
        float fi = floorf(pos);
        int i0 = (int)fi;
        int i1 = min(i0 + 1, NSn - 1);
        float fr = pos - fi;
        const float* rc = rfb + c * NSn;
        float v0 = __ldg(rc + i0), v1 = __ldg(rc + i1);
        w[q] = fmaf(fr, v1 - v0, v0);
    }

    // ---- row 0 of G = M*R: g0[lane] = sum_{m=0..112} X[m] * X[m+lane] ----
    // m = 16q + r.  vm = broadcast of w[q] lane r.
    // vk = X[m+lane]: source lane s=(r+lane)&15 supplies w[q+1] if s<r else w[q].
    float g0 = 0.0f;
    #pragma unroll
    for (int q = 0; q < 7; q++) {
        #pragma unroll
        for (int r = 0; r < 16; r++) {
            float vm  = shf(w[q], r);
            float src = (r == 0) ? w[q] : ((lane < r) ? w[q + 1] : w[q]);
            float vk  = __shfl_sync(FULLM, src, (r + lane) & 15, 16);
            g0 = fmaf(vm, vk, g0);
        }
    }
    {   // m = 112: vk = X[112+lane] = w[7] directly
        float vm = shf(w[7], 0);
        g0 = fmaf(vm, w[7], g0);
    }

    // ---- xs[lane] = sum_{j=lane}^{112+lane} X[j] = T - head - tail ----
    float ps = ((w[0] + w[1]) + (w[2] + w[3])) + ((w[4] + w[5]) + (w[6] + w[7]));
    float T = ps;
    #pragma unroll
    for (int m = 8; m; m >>= 1) T += shfx(T, m);
    // head = sum X[0..lane-1]  (all within w[0])
    float inc0 = w[0];
    #pragma unroll
    for (int d = 1; d < 16; d <<= 1) {
        float t = __shfl_up_sync(FULLM, inc0, d, 16);
        if (lane >= d) inc0 += t;
    }
    float head = inc0 - w[0];
    // tail = sum X[113+lane..127]  (all within w[7])
    float inc7 = w[7];
    #pragma unroll
    for (int d = 1; d < 16; d <<= 1) {
        float t = __shfl_up_sync(FULLM, inc7, d, 16);
        if (lane >= d) inc7 += t;
    }
    float tail = shf(inc7, 15) - inc7;
    float xs = T - head - tail;

    const float xlo = w[0];   // X[lane]
    const float xhi = w[7];   // X[112+lane]

    // ---- remaining rows via lag recurrence, lane k holds column k ----
    float g[16];
    float cur = g0;
    g[0] = cur;
    float tr = shf(cur, 0);
    #pragma unroll
    for (int l = 1; l < 16; l++) {
        float a   = shfu(cur);        // G[l-1][k-1]
        float xk1 = shfu(xlo);        // X[k-1]
        float xl1 = shf(xlo, l - 1);  // X[l-1]   (broadcast)
        float xhl = shf(xhi, l);      // X[112+l] (broadcast)
        float nxt = fmaf(xhl, xhi, fmaf(-xl1, xk1, a));
        float bnd = shf(g0, l);       // G[l][0] = G[0][l]
        nxt = (lane == 0) ? bnd : nxt;
        cur = nxt;
        g[l] = cur;                   // lane k: g[l] = G[l][k] = G[k][l]
        tr += shf(cur, l);
    }

    // ---- diagonal loading: Ghat = G + (DL/16)*tr(G) * I ----
    float d = (DLc / 16.0f) * tr;
    #pragma unroll
    for (int j = 0; j < 16; j++) g[j] += (lane == j) ? d : 0.0f;

    // ---- Cholesky, row-distributed, right-looking ----
    float lmat[16], linv[16];
    #pragma unroll
    for (int k = 0; k < 16; k++) {
        float diag = shf(g[k], k);
        float inv = rsqrtf(diag);
        inv = inv * fmaf(-0.5f * diag * inv, inv, 1.5f);  // Newton refine
        float lik = g[k] * inv;       // lane i>=k: L[i][k]; lane k: sqrt(diag)
        lmat[k] = lik;
        linv[k] = inv;                // uniform across lanes = 1/L[k][k]
        #pragma unroll
        for (int j = k + 1; j < 16; j++) {
            float ljk = shf(lik, j);
            g[j] = fmaf(-lik, ljk, g[j]);
        }
    }

    // ---- forward solve L y = 1 ----
    float s = 0.0f, yown = 0.0f;
    #pragma unroll
    for (int k = 0; k < 16; k++) {
        float t  = (1.0f - s) * linv[k];  // meaningful on lane k
        float yk = shf(t, k);
        yown = (lane == k) ? yk : yown;
        s = fmaf(lmat[k], yk, s);
    }

    // ---- backward solve L^T u = y ----
    float uown = 0.0f;
    #pragma unroll
    for (int j = 15; j >= 0; j--) {
        float part = (lane > j) ? lmat[j] * uown : 0.0f;
        part += shfx(part, 8); part += shfx(part, 4);
        part += shfx(part, 2); part += shfx(part, 1);
        float t  = (yown - part) * linv[j];  // meaningful on lane j
        float uj = shf(t, j);
        uown = (lane == j) ? uj : uown;
    }

    // ---- y = <u, xs> / (M * sum(u) + 1e-10)  (1/M scaling cancels) ----
    float dot = uown * xs;
    float sv  = uown;
    #pragma unroll
    for (int m = 8; m; m >>= 1) { dot += shfx(dot, m); sv += shfx(sv, m); }
    float y = dot / fmaf(113.0f, sv, 1e-10f);
    if (lane == 0) out[p] = y;
}

extern "C" void kernel_launch(void* const* d_in, const int* in_sizes, int n_in,
                              void* d_out, int out_size)
{
    const float* rf  = (const float*)d_in[0];
    const float* t0  = (const float*)d_in[1];
    const float* dtx = (const float*)d_in[2];
    const float* drx = (const float*)d_in[3];
    const float* fs  = (const float*)d_in[4];
    // d_in[5] = f0 (unused), d_in[7] = apod (unused, all ones in reference path)
    const float* c0  = (const float*)d_in[6];
    mvdr_kernel<<<PIX / PPB, 256>>>(rf, t0, dtx, drx, fs, c0, (float*)d_out);
}

// round 3
// speedup vs baseline: 1.8437x; 1.1527x over previous
#include <cuda_runtime.h>
#include <cuda_bf16.h>

// MVDR beamformer, R3: shuffle-minimized. Chunk layout X[8*lane+mm] makes the
// 16-lag correlation register-local (128 FMA/lane, 0 shuffles in hot loop);
// butterfly reduce distributes G row 0. Solver: forward solve fused into
// Cholesky; transpose captured during the rank-1 update so the backward solve
// needs 1 shuffle/step. ~370 shuffles/lane vs ~790 in R2 (L1TEX=89% bound).

#define FULLM 0xffffffffu

constexpr int Bn = 2, Cn = 128, NSn = 1024;
constexpr int PIX = 65536;            // B*NZ*NX
constexpr int TPB = 128;              // 8 pixels / block
constexpr int PPB = TPB / 16;
constexpr float DLc = 0.05f;

__device__ __forceinline__ float shf(float v, int s)  { return __shfl_sync(FULLM, v, s, 16); }
__device__ __forceinline__ float shfu(float v)        { return __shfl_up_sync(FULLM, v, 1, 16); }
__device__ __forceinline__ float shfx(float v, int m) { return __shfl_xor_sync(FULLM, v, m, 16); }

__global__ __launch_bounds__(TPB) void mvdr_kernel(
    const float* __restrict__ rf,   // [B, C, NS]
    const float* __restrict__ t0,   // [B]
    const float* __restrict__ dtx,  // [B, NZ, NX]
    const float* __restrict__ drx,  // [C, NZ, NX]
    const float* __restrict__ fsp,  // [1]
    const float* __restrict__ c0p,  // [1]
    float* __restrict__ out)        // [B, NZ, NX]
{
    const int tid  = threadIdx.x;
    const int grp  = tid >> 4;
    const int lane = tid & 15;
    const int p    = blockIdx.x * PPB + grp;
    const int b    = p >> 15;
    const int rem  = p & 32767;

    const float fs   = __ldg(fsp);
    const float ic0  = 1.0f / __ldg(c0p);
    const float t0v  = __ldg(t0 + b);
    const float dtxv = __ldg(dtx + b * 32768 + rem);
    const float* rfb = rf + b * (Cn * NSn);

    // ---- delay-and-interpolate, chunk layout: xe[mm] = X[8*lane+mm] ----
    float xe[24];
    #pragma unroll
    for (int mm = 0; mm < 8; mm++) {
        int c = 8 * lane + mm;
        float pos = fs * ((dtxv + __ldg(drx + c * 32768 + rem)) * ic0 + t0v);
        pos = fminf(fmaxf(pos, 0.0f), 1023.0f);
        float fi = floorf(pos);
        int i0 = (int)fi;
        int i1 = min(i0 + 1, NSn - 1);
        float fr = pos - fi;
        const float* rc = rfb + c * NSn;
        float v0 = __ldg(rc + i0), v1 = __ldg(rc + i1);
        xe[mm] = fmaf(fr, v1 - v0, v0);
    }
    // neighbor chunks: xe[8+i] = X[8*(lane+1)+i], xe[16+i] = X[8*(lane+2)+i]
    #pragma unroll
    for (int i = 0; i < 8; i++) xe[8 + i]  = shf(xe[i], lane + 1);
    #pragma unroll
    for (int i = 0; i < 8; i++) xe[16 + i] = shf(xe[i], lane + 2);

    // ---- register-local correlation: acc[k] = sum over own m of X[m]X[m+k] ----
    float acc[16];
    #pragma unroll
    for (int k = 0; k < 16; k++) acc[k] = 0.0f;
    #pragma unroll
    for (int mm = 0; mm < 8; mm++) {
        if (8 * lane + mm <= 112) {       // m <= M-1 = 112
            float xm = xe[mm];
            #pragma unroll
            for (int k = 0; k < 16; k++)
                acc[k] = fmaf(xm, xe[mm + k], acc[k]);
        }
    }
    // butterfly reduce each lag across the 16 lanes, then pick own lag
    #pragma unroll
    for (int k = 0; k < 16; k++) {
        float a = acc[k];
        a += shfx(a, 8); a += shfx(a, 4); a += shfx(a, 2); a += shfx(a, 1);
        acc[k] = a;
    }
    float g0 = acc[0];
    #pragma unroll
    for (int k = 1; k < 16; k++) if (lane == k) g0 = acc[k];

    // ---- inclusive prefix of X (distributed), for xs window sums ----
    float P[8];
    P[0] = xe[0];
    #pragma unroll
    for (int mm = 1; mm < 8; mm++) P[mm] = P[mm - 1] + xe[mm];
    float e = P[7];
    #pragma unroll
    for (int d = 1; d < 16; d <<= 1) {
        float t = __shfl_up_sync(FULLM, e, d, 16);
        if (lane >= d) e += t;
    }
    float base = e - P[7];
    float pref[8];
    #pragma unroll
    for (int mm = 0; mm < 8; mm++) pref[mm] = base + P[mm];  // incl prefix at 8*lane+mm

    // ---- cross-layout gathers: value at global index j -> lane j>>3, reg j&7 ----
    const int sr = lane & 7;
    const int sl_lo = lane >> 3;
    const int sl_hi = 14 + (lane >> 3);
    float xlo = 0.0f, xhi = 0.0f, ph = 0.0f;
    #pragma unroll
    for (int i = 0; i < 8; i++) {
        float ta = shf(xe[i],   sl_lo); if (sr == i) xlo = ta;   // X[lane]
        float tb = shf(xe[i],   sl_hi); if (sr == i) xhi = tb;   // X[112+lane]
        float tc = shf(pref[i], sl_hi); if (sr == i) ph  = tc;   // prefix(112+lane)
    }
    int jm = lane - 1;
    int sl_l = (jm >= 0) ? (jm >> 3) : 0;
    int sr_l = jm & 7;
    float pl = 0.0f;
    #pragma unroll
    for (int i = 0; i < 8; i++) {
        float t = shf(pref[i], sl_l); if (sr_l == i) pl = t;     // prefix(lane-1)
    }
    if (lane == 0) pl = 0.0f;
    float xs = ph - pl;   // sum_{j=lane}^{112+lane} X[j]

    // ---- remaining rows of G via lag recurrence (lane k holds column k) ----
    float g[16];
    float cur = g0;
    g[0] = cur;
    #pragma unroll
    for (int l = 1; l < 16; l++) {
        float a   = shfu(cur);        // G[l-1][k-1]
        float xk1 = shfu(xlo);        // X[k-1]
        float xl1 = shf(xlo, l - 1);  // X[l-1]
        float xhl = shf(xhi, l);      // X[112+l]
        float nxt = fmaf(xhl, xhi, fmaf(-xl1, xk1, a));
        float bnd = shf(g0, l);       // G[l][0]
        nxt = (lane == 0) ? bnd : nxt;
        cur = nxt;
        g[l] = cur;
    }

    // ---- trace via select + butterfly ----
    float dd = g[0];
    #pragma unroll
    for (int j = 1; j < 16; j++) if (lane == j) dd = g[j];   // G[lane][lane]
    float tr = dd;
    tr += shfx(tr, 8); tr += shfx(tr, 4); tr += shfx(tr, 2); tr += shfx(tr, 1);
    float dload = (DLc / 16.0f) * tr;
    #pragma unroll
    for (int j = 0; j < 16; j++) g[j] += (lane == j) ? dload : 0.0f;

    // ---- Cholesky (row-distributed) + fused forward solve + transpose capture ----
    float linv[16], ltr[16];
    #pragma unroll
    for (int j = 0; j < 16; j++) ltr[j] = 0.0f;
    float s = 0.0f, yown = 0.0f;
    #pragma unroll
    for (int k = 0; k < 16; k++) {
        float diag = shf(g[k], k);
        float inv = rsqrtf(diag);
        inv = inv * fmaf(-0.5f * diag * inv, inv, 1.5f);   // Newton refine
        float lik = g[k] * inv;        // lane i: L[i][k] (valid i>=k)
        linv[k] = inv;
        // forward solve L y = 1, step k
        float t = (1.0f - s) * inv;    // meaningful on lane k
        float yk = shf(t, k);
        if (lane == k) yown = yk;
        s = fmaf(lik, yk, s);
        // rank-1 update; lane k captures column k transpose: ltr[j] = L[j][k]
        #pragma unroll
        for (int j = k + 1; j < 16; j++) {
            float ljk = shf(lik, j);
            if (lane == k) ltr[j] = ljk;
            g[j] = fmaf(-lik, ljk, g[j]);
        }
    }

    // ---- backward solve L^T u = y: 1 shuffle per step ----
    float sacc = 0.0f, uown = 0.0f;
    #pragma unroll
    for (int j = 15; j >= 0; j--) {
        float t = (yown - sacc) * linv[j];   // meaningful on lane j
        float uj = shf(t, j);
        if (lane == j) uown = uj;
        sacc = fmaf(ltr[j], uj, sacc);       // lane x<j accumulates L[j][x]*u_j
    }

    // ---- y = <u, xs> / (M * sum(u) + 1e-10) ----
    float dot = uown * xs;
    float sv  = uown;
    #pragma unroll
    for (int m = 8; m; m >>= 1) { dot += shfx(dot, m); sv += shfx(sv, m); }
    float y = dot / fmaf(113.0f, sv, 1e-10f);
    if (lane == 0) out[p] = y;
}

extern "C" void kernel_launch(void* const* d_in, const int* in_sizes, int n_in,
                              void* d_out, int out_size)
{
    const float* rf  = (const float*)d_in[0];
    const float* t0  = (const float*)d_in[1];
    const float* dtx = (const float*)d_in[2];
    const float* drx = (const float*)d_in[3];
    const float* fs  = (const float*)d_in[4];
    // d_in[5] = f0 (unused), d_in[7] = apod (unused, all-ones)
    const float* c0  = (const float*)d_in[6];
    mvdr_kernel<<<PIX / PPB, TPB>>>(rf, t0, dtx, drx, fs, c0, (float*)d_out);
}

// round 4
// speedup vs baseline: 1.9165x; 1.0395x over previous
#include <cuda_runtime.h>
#include <cuda_bf16.h>

// MVDR beamformer, R4. l1tex is the wall (gathers + shuffles share it):
//  - rf interpolation: one aligned float4 load covers v0,v1 (75%); predicated
//    scalar patch for the 25% straddle case. Halves rf gather wavefronts.
//  - G row 0 reduce: butterfly allreduce -> reduce-scatter (64 -> 15 shuffles).
//  - xs from scans of xlo/xhi + one chunk scan (kills prefix-array gathers).
//  - lag recurrence: loop-invariant shfu hoisted (4 shuffles/step).

#define FULLM 0xffffffffu

constexpr int Bn = 2, Cn = 128, NSn = 1024;
constexpr int PIX = 65536;            // B*NZ*NX
constexpr int TPB = 128;              // 8 pixels / block
constexpr int PPB = TPB / 16;
constexpr float DLc = 0.05f;

__device__ __forceinline__ float shf(float v, int s)  { return __shfl_sync(FULLM, v, s, 16); }
__device__ __forceinline__ float shfu(float v)        { return __shfl_up_sync(FULLM, v, 1, 16); }
__device__ __forceinline__ float shfx(float v, int m) { return __shfl_xor_sync(FULLM, v, m, 16); }

__global__ __launch_bounds__(TPB) void mvdr_kernel(
    const float* __restrict__ rf,   // [B, C, NS]
    const float* __restrict__ t0,   // [B]
    const float* __restrict__ dtx,  // [B, NZ, NX]
    const float* __restrict__ drx,  // [C, NZ, NX]
    const float* __restrict__ fsp,  // [1]
    const float* __restrict__ c0p,  // [1]
    float* __restrict__ out)        // [B, NZ, NX]
{
    const int tid  = threadIdx.x;
    const int grp  = tid >> 4;
    const int lane = tid & 15;
    const int p    = blockIdx.x * PPB + grp;
    const int b    = p >> 15;
    const int rem  = p & 32767;

    const float fs   = __ldg(fsp);
    const float ic0  = 1.0f / __ldg(c0p);
    const float t0v  = __ldg(t0 + b);
    const float dtxv = __ldg(dtx + b * 32768 + rem);
    const float* rfb = rf + b * (Cn * NSn);

    // ---- delay-and-interpolate, chunk layout: xe[mm] = X[8*lane+mm] ----
    float xe[24];
    #pragma unroll
    for (int mm = 0; mm < 8; mm++) {
        int c = 8 * lane + mm;
        float pos = fs * ((dtxv + __ldg(drx + c * 32768 + rem)) * ic0 + t0v);
        pos = fminf(fmaxf(pos, 0.0f), 1023.0f);
        float fi = floorf(pos);
        int i0 = (int)fi;
        float fr = pos - fi;
        const float* rc = rfb + c * NSn;
        int a = i0 & ~3;
        int d = i0 - a;                       // 0..3
        float4 q = __ldg((const float4*)(rc + a));
        float v0 = (d == 0) ? q.x : (d == 1) ? q.y : (d == 2) ? q.z : q.w;
        float v1 = (d == 0) ? q.y : (d == 1) ? q.z : (d == 2) ? q.w : 0.0f;
        if (d == 3) {
            int i1 = min(i0 + 1, NSn - 1);
            v1 = __ldg(rc + i1);
        }
        xe[mm] = fmaf(fr, v1 - v0, v0);
    }
    // neighbor chunks: xe[8+i] = X[8*(lane+1)+i], xe[16+i] = X[8*(lane+2)+i]
    #pragma unroll
    for (int i = 0; i < 8; i++) xe[8 + i]  = shf(xe[i], lane + 1);
    #pragma unroll
    for (int i = 0; i < 8; i++) xe[16 + i] = shf(xe[i], lane + 2);

    // ---- register-local correlation: acc[k] = sum over own m of X[m]X[m+k] ----
    float acc[16];
    #pragma unroll
    for (int k = 0; k < 16; k++) acc[k] = 0.0f;
    #pragma unroll
    for (int mm = 0; mm < 8; mm++) {
        if (8 * lane + mm <= 112) {       // m <= M-1 = 112
            float xm = xe[mm];
            #pragma unroll
            for (int k = 0; k < 16; k++)
                acc[k] = fmaf(xm, xe[mm + k], acc[k]);
        }
    }

    // ---- reduce-scatter: lag k -> lane k (15 shuffles) ----
    // After stage mask m, slot j holds lag (lane & processed_bits) + j.
    {
        float a2[8];
        #pragma unroll
        for (int j = 0; j < 8; j++) {
            float sel  = (lane & 8) ? acc[j] : acc[8 + j];
            float got  = shfx(sel, 8);
            float keep = (lane & 8) ? acc[8 + j] : acc[j];
            a2[j] = keep + got;
        }
        float a3[4];
        #pragma unroll
        for (int j = 0; j < 4; j++) {
            float sel  = (lane & 4) ? a2[j] : a2[4 + j];
            float got  = shfx(sel, 4);
            float keep = (lane & 4) ? a2[4 + j] : a2[j];
            a3[j] = keep + got;
        }
        float a4[2];
        #pragma unroll
        for (int j = 0; j < 2; j++) {
            float sel  = (lane & 2) ? a3[j] : a3[2 + j];
            float got  = shfx(sel, 2);
            float keep = (lane & 2) ? a3[2 + j] : a3[j];
            a4[j] = keep + got;
        }
        float sel  = (lane & 1) ? a4[0] : a4[1];
        float got  = shfx(sel, 1);
        float keep = (lane & 1) ? a4[1] : a4[0];
        acc[0] = keep + got;               // g0 = G[0][lane]
    }
    float g0 = acc[0];

    // ---- cross-layout gathers: xlo = X[lane], xhi = X[112+lane] ----
    const int sr    = lane & 7;
    const int sl_lo = lane >> 3;
    const int sl_hi = 14 + (lane >> 3);
    float xlo = 0.0f, xhi = 0.0f;
    #pragma unroll
    for (int i = 0; i < 8; i++) {
        float ta = shf(xe[i], sl_lo); if (sr == i) xlo = ta;
        float tb = shf(xe[i], sl_hi); if (sr == i) xhi = tb;
    }

    // ---- window sums xs via scans ----
    float cs = ((xe[0] + xe[1]) + (xe[2] + xe[3])) + ((xe[4] + xe[5]) + (xe[6] + xe[7]));
    float S = cs;                          // inclusive scan of chunk sums
    #pragma unroll
    for (int d = 1; d < 16; d <<= 1) {
        float t = __shfl_up_sync(FULLM, S, d, 16);
        if (lane >= d) S += t;
    }
    float P111 = shf(S, 13);               // prefix over X[0..111]
    float slo = xlo;                       // inclusive scan -> prefix X[0..lane]
    #pragma unroll
    for (int d = 1; d < 16; d <<= 1) {
        float t = __shfl_up_sync(FULLM, slo, d, 16);
        if (lane >= d) slo += t;
    }
    float shi = xhi;                       // inclusive scan -> sum X[112..112+lane]
    #pragma unroll
    for (int d = 1; d < 16; d <<= 1) {
        float t = __shfl_up_sync(FULLM, shi, d, 16);
        if (lane >= d) shi += t;
    }
    float xs = P111 + shi - slo + xlo;     // sum_{j=lane}^{112+lane} X[j]

    // ---- remaining rows of G via lag recurrence (lane k holds column k) ----
    float g[16];
    float cur = g0;
    g[0] = cur;
    const float xk1 = shfu(xlo);           // X[k-1] (loop-invariant)
    #pragma unroll
    for (int l = 1; l < 16; l++) {
        float a   = shfu(cur);             // G[l-1][k-1]
        float xl1 = shf(xlo, l - 1);       // X[l-1]
        float xhl = shf(xhi, l);           // X[112+l]
        float nxt = fmaf(xhl, xhi, fmaf(-xl1, xk1, a));
        float bnd = shf(g0, l);            // G[l][0]
        nxt = (lane == 0) ? bnd : nxt;
        cur = nxt;
        g[l] = cur;
    }

    // ---- trace + diagonal loading ----
    float dd = g[0];
    #pragma unroll
    for (int j = 1; j < 16; j++) if (lane == j) dd = g[j];   // G[lane][lane]
    float tr = dd;
    tr += shfx(tr, 8); tr += shfx(tr, 4); tr += shfx(tr, 2); tr += shfx(tr, 1);
    float dload = (DLc / 16.0f) * tr;
    #pragma unroll
    for (int j = 0; j < 16; j++) g[j] += (lane == j) ? dload : 0.0f;

    // ---- Cholesky (row-distributed) + fused forward solve + transpose capture ----
    float linv[16], ltr[16];
    #pragma unroll
    for (int j = 0; j < 16; j++) ltr[j] = 0.0f;
    float s = 0.0f, yown = 0.0f;
    #pragma unroll
    for (int k = 0; k < 16; k++) {
        float diag = shf(g[k], k);
        float inv = rsqrtf(diag);
        inv = inv * fmaf(-0.5f * diag * inv, inv, 1.5f);   // Newton refine
        float lik = g[k] * inv;        // lane i: L[i][k] (valid i>=k)
        linv[k] = inv;
        float t = (1.0f - s) * inv;    // meaningful on lane k
        float yk = shf(t, k);
        if (lane == k) yown = yk;
        s = fmaf(lik, yk, s);
        #pragma unroll
        for (int j = k + 1; j < 16; j++) {
            float ljk = shf(lik, j);
            if (lane == k) ltr[j] = ljk;     // lane k captures column k: L[j][k]
            g[j] = fmaf(-lik, ljk, g[j]);
        }
    }

    // ---- backward solve L^T u = y: 1 shuffle per step ----
    float sacc = 0.0f, uown = 0.0f;
    #pragma unroll
    for (int j = 15; j >= 0; j--) {
        float t = (yown - sacc) * linv[j];   // meaningful on lane j
        float uj = shf(t, j);
        if (lane == j) uown = uj;
        sacc = fmaf(ltr[j], uj, sacc);
    }

    // ---- y = <u, xs> / (M * sum(u) + 1e-10) ----
    float dot = uown * xs;
    float sv  = uown;
    #pragma unroll
    for (int m = 8; m; m >>= 1) { dot += shfx(dot, m); sv += shfx(sv, m); }
    float y = dot / fmaf(113.0f, sv, 1e-10f);
    if (lane == 0) out[p] = y;
}

extern "C" void kernel_launch(void* const* d_in, const int* in_sizes, int n_in,
                              void* d_out, int out_size)
{
    const float* rf  = (const float*)d_in[0];
    const float* t0  = (const float*)d_in[1];
    const float* dtx = (const float*)d_in[2];
    const float* drx = (const float*)d_in[3];
    const float* fs  = (const float*)d_in[4];
    // d_in[5] = f0 (unused), d_in[7] = apod (unused, all-ones)
    const float* c0  = (const float*)d_in[6];
    mvdr_kernel<<<PIX / PPB, TPB>>>(rf, t0, dtx, drx, fs, c0, (float*)d_out);
}

// round 5
// speedup vs baseline: 2.1005x; 1.0960x over previous
#include <cuda_runtime.h>
#include <cuda_bf16.h>

// MVDR beamformer, R5. drx gather was ~256 l1tex wavefronts/warp (32 scattered
// channel rows per LDG). A block's 8 pixels need the dense tile drx[0..127][rem0..rem0+7],
// so stage it: coalesced LDG (4 wf), conflict-free STS, 4-way LDS reads ->
// 72 wf/warp total. rf float4 gather, reduce-scatter row 0, lag recurrence,
// fused Cholesky + solves unchanged from R4 (rel_err 1.3e-7).

#define FULLM 0xffffffffu

constexpr int Bn = 2, Cn = 128, NSn = 1024;
constexpr int PIX = 65536;            // B*NZ*NX
constexpr int TPB = 128;              // 8 pixels / block
constexpr int PPB = TPB / 16;
constexpr int DPAD = 132;             // smem row pad (conflict-free STS, 4-way LDS)
constexpr float DLc = 0.05f;

__device__ __forceinline__ float shf(float v, int s)  { return __shfl_sync(FULLM, v, s, 16); }
__device__ __forceinline__ float shfu(float v)        { return __shfl_up_sync(FULLM, v, 1, 16); }
__device__ __forceinline__ float shfx(float v, int m) { return __shfl_xor_sync(FULLM, v, m, 16); }

__global__ __launch_bounds__(TPB) void mvdr_kernel(
    const float* __restrict__ rf,   // [B, C, NS]
    const float* __restrict__ t0,   // [B]
    const float* __restrict__ dtx,  // [B, NZ, NX]
    const float* __restrict__ drx,  // [C, NZ, NX]
    const float* __restrict__ fsp,  // [1]
    const float* __restrict__ c0p,  // [1]
    float* __restrict__ out)        // [B, NZ, NX]
{
    __shared__ float sdrx[PPB * DPAD];   // [pixel-in-block][channel]

    const int tid  = threadIdx.x;
    const int grp  = tid >> 4;
    const int lane = tid & 15;
    const int p    = blockIdx.x * PPB + grp;
    const int b    = p >> 15;            // uniform across block (32768 % 8 == 0)
    const int rem  = p & 32767;
    const int rem0 = (blockIdx.x * PPB) & 32767;

    // ---- stage drx tile [128 channels][8 pixels], coalesced ----
    #pragma unroll
    for (int j = 0; j < 8; j++) {
        int idx = j * TPB + tid;         // 0..1023
        int c   = idx >> 3;
        int i   = idx & 7;
        sdrx[i * DPAD + c] = __ldg(drx + c * 32768 + rem0 + i);
    }
    __syncthreads();

    const float fs   = __ldg(fsp);
    const float ic0  = 1.0f / __ldg(c0p);
    const float t0v  = __ldg(t0 + b);
    const float dtxv = __ldg(dtx + b * 32768 + rem);
    const float* rfb = rf + b * (Cn * NSn);
    const float* myrx = sdrx + grp * DPAD;

    // ---- delay-and-interpolate, chunk layout: xe[mm] = X[8*lane+mm] ----
    float xe[24];
    #pragma unroll
    for (int mm = 0; mm < 8; mm++) {
        int c = 8 * lane + mm;
        float pos = fs * ((dtxv + myrx[c]) * ic0 + t0v);
        pos = fminf(fmaxf(pos, 0.0f), 1023.0f);
        float fi = floorf(pos);
        int i0 = (int)fi;
        float fr = pos - fi;
        const float* rc = rfb + c * NSn;
        int a = i0 & ~3;
        int d = i0 - a;                       // 0..3
        float4 q = __ldg((const float4*)(rc + a));
        float v0 = (d == 0) ? q.x : (d == 1) ? q.y : (d == 2) ? q.z : q.w;
        float v1 = (d == 0) ? q.y : (d == 1) ? q.z : (d == 2) ? q.w : 0.0f;
        if (d == 3) {
            int i1 = min(i0 + 1, NSn - 1);
            v1 = __ldg(rc + i1);
        }
        xe[mm] = fmaf(fr, v1 - v0, v0);
    }
    // neighbor chunks: xe[8+i] = X[8*(lane+1)+i], xe[16+i] = X[8*(lane+2)+i]
    #pragma unroll
    for (int i = 0; i < 8; i++) xe[8 + i]  = shf(xe[i], lane + 1);
    #pragma unroll
    for (int i = 0; i < 8; i++) xe[16 + i] = shf(xe[i], lane + 2);

    // ---- register-local correlation: acc[k] = sum over own m of X[m]X[m+k] ----
    float acc[16];
    #pragma unroll
    for (int k = 0; k < 16; k++) acc[k] = 0.0f;
    #pragma unroll
    for (int mm = 0; mm < 8; mm++) {
        if (8 * lane + mm <= 112) {       // m <= M-1 = 112
            float xm = xe[mm];
            #pragma unroll
            for (int k = 0; k < 16; k++)
                acc[k] = fmaf(xm, xe[mm + k], acc[k]);
        }
    }

    // ---- reduce-scatter: lag k -> lane k (15 shuffles) ----
    {
        float a2[8];
        #pragma unroll
        for (int j = 0; j < 8; j++) {
            float sel  = (lane & 8) ? acc[j] : acc[8 + j];
            float got  = shfx(sel, 8);
            float keep = (lane & 8) ? acc[8 + j] : acc[j];
            a2[j] = keep + got;
        }
        float a3[4];
        #pragma unroll
        for (int j = 0; j < 4; j++) {
            float sel  = (lane & 4) ? a2[j] : a2[4 + j];
            float got  = shfx(sel, 4);
            float keep = (lane & 4) ? a2[4 + j] : a2[j];
            a3[j] = keep + got;
        }
        float a4[2];
        #pragma unroll
        for (int j = 0; j < 2; j++) {
            float sel  = (lane & 2) ? a3[j] : a3[2 + j];
            float got  = shfx(sel, 2);
            float keep = (lane & 2) ? a3[2 + j] : a3[j];
            a4[j] = keep + got;
        }
        float sel  = (lane & 1) ? a4[0] : a4[1];
        float got  = shfx(sel, 1);
        float keep = (lane & 1) ? a4[1] : a4[0];
        acc[0] = keep + got;               // g0 = G[0][lane]
    }
    float g0 = acc[0];

    // ---- cross-layout gathers: xlo = X[lane], xhi = X[112+lane] ----
    const int sr    = lane & 7;
    const int sl_lo = lane >> 3;
    const int sl_hi = 14 + (lane >> 3);
    float xlo = 0.0f, xhi = 0.0f;
    #pragma unroll
    for (int i = 0; i < 8; i++) {
        float ta = shf(xe[i], sl_lo); if (sr == i) xlo = ta;
        float tb = shf(xe[i], sl_hi); if (sr == i) xhi = tb;
    }

    // ---- window sums xs via scans ----
    float cs = ((xe[0] + xe[1]) + (xe[2] + xe[3])) + ((xe[4] + xe[5]) + (xe[6] + xe[7]));
    float S = cs;                          // inclusive scan of chunk sums
    #pragma unroll
    for (int d = 1; d < 16; d <<= 1) {
        float t = __shfl_up_sync(FULLM, S, d, 16);
        if (lane >= d) S += t;
    }
    float P111 = shf(S, 13);               // prefix over X[0..111]
    float slo = xlo;                       // inclusive scan -> prefix X[0..lane]
    #pragma unroll
    for (int d = 1; d < 16; d <<= 1) {
        float t = __shfl_up_sync(FULLM, slo, d, 16);
        if (lane >= d) slo += t;
    }
    float shi = xhi;                       // inclusive scan -> sum X[112..112+lane]
    #pragma unroll
    for (int d = 1; d < 16; d <<= 1) {
        float t = __shfl_up_sync(FULLM, shi, d, 16);
        if (lane >= d) shi += t;
    }
    float xs = P111 + shi - slo + xlo;     // sum_{j=lane}^{112+lane} X[j]

    // ---- remaining rows of G via lag recurrence (lane k holds column k) ----
    float g[16];
    float cur = g0;
    g[0] = cur;
    const float xk1 = shfu(xlo);           // X[k-1] (loop-invariant)
    #pragma unroll
    for (int l = 1; l < 16; l++) {
        float a   = shfu(cur);             // G[l-1][k-1]
        float xl1 = shf(xlo, l - 1);       // X[l-1]
        float xhl = shf(xhi, l);           // X[112+l]
        float nxt = fmaf(xhl, xhi, fmaf(-xl1, xk1, a));
        float bnd = shf(g0, l);            // G[l][0]
        nxt = (lane == 0) ? bnd : nxt;
        cur = nxt;
        g[l] = cur;
    }

    // ---- trace + diagonal loading ----
    float dd = g[0];
    #pragma unroll
    for (int j = 1; j < 16; j++) if (lane == j) dd = g[j];   // G[lane][lane]
    float tr = dd;
    tr += shfx(tr, 8); tr += shfx(tr, 4); tr += shfx(tr, 2); tr += shfx(tr, 1);
    float dload = (DLc / 16.0f) * tr;
    #pragma unroll
    for (int j = 0; j < 16; j++) g[j] += (lane == j) ? dload : 0.0f;

    // ---- Cholesky (row-distributed) + fused forward solve + transpose capture ----
    float linv[16], ltr[16];
    #pragma unroll
    for (int j = 0; j < 16; j++) ltr[j] = 0.0f;
    float s = 0.0f, yown = 0.0f;
    #pragma unroll
    for (int k = 0; k < 16; k++) {
        float diag = shf(g[k], k);
        float inv = rsqrtf(diag);
        inv = inv * fmaf(-0.5f * diag * inv, inv, 1.5f);   // Newton refine
        float lik = g[k] * inv;        // lane i: L[i][k] (valid i>=k)
        linv[k] = inv;
        float t = (1.0f - s) * inv;    // meaningful on lane k
        float yk = shf(t, k);
        if (lane == k) yown = yk;
        s = fmaf(lik, yk, s);
        #pragma unroll
        for (int j = k + 1; j < 16; j++) {
            float ljk = shf(lik, j);
            if (lane == k) ltr[j] = ljk;     // lane k captures column k: L[j][k]
            g[j] = fmaf(-lik, ljk, g[j]);
        }
    }

    // ---- backward solve L^T u = y: 1 shuffle per step ----
    float sacc = 0.0f, uown = 0.0f;
    #pragma unroll
    for (int j = 15; j >= 0; j--) {
        float t = (yown - sacc) * linv[j];   // meaningful on lane j
        float uj = shf(t, j);
        if (lane == j) uown = uj;
        sacc = fmaf(ltr[j], uj, sacc);
    }

    // ---- y = <u, xs> / (M * sum(u) + 1e-10) ----
    float dot = uown * xs;
    float sv  = uown;
    #pragma unroll
    for (int m = 8; m; m >>= 1) { dot += shfx(dot, m); sv += shfx(sv, m); }
    float y = dot / fmaf(113.0f, sv, 1e-10f);
    if (lane == 0) out[p] = y;
}

extern "C" void kernel_launch(void* const* d_in, const int* in_sizes, int n_in,
                              void* d_out, int out_size)
{
    const float* rf  = (const float*)d_in[0];
    const float* t0  = (const float*)d_in[1];
    const float* dtx = (const float*)d_in[2];
    const float* drx = (const float*)d_in[3];
    const float* fs  = (const float*)d_in[4];
    // d_in[5] = f0 (unused), d_in[7] = apod (unused, all-ones)
    const float* c0  = (const float*)d_in[6];
    mvdr_kernel<<<PIX / PPB, TPB>>>(rf, t0, dtx, drx, fs, c0, (float*)d_out);
}

// round 6
// speedup vs baseline: 2.1724x; 1.0342x over previous
#include <cuda_runtime.h>
#include <cuda_bf16.h>

// MVDR beamformer, R6. Wavefront cuts on the binding l1tex pipe:
//  (1) rf pair-prepass into static __device__ float2 buffer: every gather is
//      one aligned LDG.64 (no float4 straddle patch, no component selects).
//  (2) Cholesky column broadcast through smem (STS + LDS.128 quads, double-
//      buffered, 1 syncwarp/step) replacing the 120-shuffle allgather.
//  (3) staged drx read as 2x LDS.128 (DPAD=136, 16B-aligned rows).

#define FULLM 0xffffffffu

constexpr int Bn = 2, Cn = 128, NSn = 1024;
constexpr int PIX = 65536;            // B*NZ*NX
constexpr int TPB = 128;              // 8 pixels / block
constexpr int PPB = TPB / 16;
constexpr int DPAD = 136;             // 136*4 = 544B rows: 16B aligned
constexpr float DLc = 0.05f;

__device__ float2 rf2buf[Bn * Cn * NSn];   // 2 MB static scratch

__global__ __launch_bounds__(256) void prep_kernel(const float* __restrict__ rf)
{
    int i = blockIdx.x * 256 + threadIdx.x;       // over Bn*Cn*NSn = 262144
    int s = i & (NSn - 1);
    float a = __ldg(rf + i);
    float b2 = (s == NSn - 1) ? a : __ldg(rf + i + 1);
    rf2buf[i] = make_float2(a, b2);
}

__device__ __forceinline__ float shf(float v, int s)  { return __shfl_sync(FULLM, v, s, 16); }
__device__ __forceinline__ float shfu(float v)        { return __shfl_up_sync(FULLM, v, 1, 16); }
__device__ __forceinline__ float shfx(float v, int m) { return __shfl_xor_sync(FULLM, v, m, 16); }

__global__ __launch_bounds__(TPB) void mvdr_kernel(
    const float* __restrict__ t0,   // [B]
    const float* __restrict__ dtx,  // [B, NZ, NX]
    const float* __restrict__ drx,  // [C, NZ, NX]
    const float* __restrict__ fsp,  // [1]
    const float* __restrict__ c0p,  // [1]
    float* __restrict__ out)        // [B, NZ, NX]
{
    __shared__ __align__(16) float sdrx[PPB * DPAD];   // [pixel][channel]
    __shared__ __align__(16) float scol[2][PPB][16];   // Cholesky column bcast

    const int tid  = threadIdx.x;
    const int grp  = tid >> 4;
    const int lane = tid & 15;
    const int p    = blockIdx.x * PPB + grp;
    const int b    = p >> 15;            // uniform across block (32768 % 8 == 0)
    const int rem  = p & 32767;
    const int rem0 = (blockIdx.x * PPB) & 32767;

    // ---- stage drx tile [128 channels][8 pixels], coalesced ----
    #pragma unroll
    for (int j = 0; j < 8; j++) {
        int idx = j * TPB + tid;         // 0..1023
        int c   = idx >> 3;
        int i   = idx & 7;
        sdrx[i * DPAD + c] = __ldg(drx + c * 32768 + rem0 + i);
    }
    __syncthreads();

    const float fs   = __ldg(fsp);
    const float ic0  = 1.0f / __ldg(c0p);
    const float t0v  = __ldg(t0 + b);
    const float dtxv = __ldg(dtx + b * 32768 + rem);

    // my 8 channel delays via 2x LDS.128
    const float4* myrx4 = (const float4*)(sdrx + grp * DPAD);
    float4 r0 = myrx4[2 * lane], r1 = myrx4[2 * lane + 1];
    float del[8] = {r0.x, r0.y, r0.z, r0.w, r1.x, r1.y, r1.z, r1.w};

    // ---- delay-and-interpolate, chunk layout: xe[mm] = X[8*lane+mm] ----
    const float2* rb = rf2buf + (size_t)b * (Cn * NSn) + (size_t)(8 * lane) * NSn;
    float xe[24];
    #pragma unroll
    for (int mm = 0; mm < 8; mm++) {
        float pos = fs * ((dtxv + del[mm]) * ic0 + t0v);
        pos = fminf(fmaxf(pos, 0.0f), 1023.0f);
        float fi = floorf(pos);
        int i0 = (int)fi;
        float fr = pos - fi;
        float2 v = __ldg((const float2*)(rb + mm * NSn + i0));
        xe[mm] = fmaf(fr, v.y - v.x, v.x);
    }
    // neighbor chunks: xe[8+i] = X[8*(lane+1)+i], xe[16+i] = X[8*(lane+2)+i]
    #pragma unroll
    for (int i = 0; i < 8; i++) xe[8 + i]  = shf(xe[i], lane + 1);
    #pragma unroll
    for (int i = 0; i < 8; i++) xe[16 + i] = shf(xe[i], lane + 2);

    // ---- register-local correlation: acc[k] = sum over own m of X[m]X[m+k] ----
    float acc[16];
    #pragma unroll
    for (int k = 0; k < 16; k++) acc[k] = 0.0f;
    #pragma unroll
    for (int mm = 0; mm < 8; mm++) {
        if (8 * lane + mm <= 112) {       // m <= M-1 = 112
            float xm = xe[mm];
            #pragma unroll
            for (int k = 0; k < 16; k++)
                acc[k] = fmaf(xm, xe[mm + k], acc[k]);
        }
    }

    // ---- reduce-scatter: lag k -> lane k (15 shuffles) ----
    {
        float a2[8];
        #pragma unroll
        for (int j = 0; j < 8; j++) {
            float sel  = (lane & 8) ? acc[j] : acc[8 + j];
            float got  = shfx(sel, 8);
            float keep = (lane & 8) ? acc[8 + j] : acc[j];
            a2[j] = keep + got;
        }
        float a3[4];
        #pragma unroll
        for (int j = 0; j < 4; j++) {
            float sel  = (lane & 4) ? a2[j] : a2[4 + j];
            float got  = shfx(sel, 4);
            float keep = (lane & 4) ? a2[4 + j] : a2[j];
            a3[j] = keep + got;
        }
        float a4[2];
        #pragma unroll
        for (int j = 0; j < 2; j++) {
            float sel  = (lane & 2) ? a3[j] : a3[2 + j];
            float got  = shfx(sel, 2);
            float keep = (lane & 2) ? a3[2 + j] : a3[j];
            a4[j] = keep + got;
        }
        float sel  = (lane & 1) ? a4[0] : a4[1];
        float got  = shfx(sel, 1);
        float keep = (lane & 1) ? a4[1] : a4[0];
        acc[0] = keep + got;               // g0 = G[0][lane]
    }
    float g0 = acc[0];

    // ---- cross-layout gathers: xlo = X[lane], xhi = X[112+lane] ----
    const int sr    = lane & 7;
    const int sl_lo = lane >> 3;
    const int sl_hi = 14 + (lane >> 3);
    float xlo = 0.0f, xhi = 0.0f;
    #pragma unroll
    for (int i = 0; i < 8; i++) {
        float ta = shf(xe[i], sl_lo); if (sr == i) xlo = ta;
        float tb = shf(xe[i], sl_hi); if (sr == i) xhi = tb;
    }

    // ---- window sums xs via scans ----
    float cs = ((xe[0] + xe[1]) + (xe[2] + xe[3])) + ((xe[4] + xe[5]) + (xe[6] + xe[7]));
    float S = cs;                          // inclusive scan of chunk sums
    #pragma unroll
    for (int d = 1; d < 16; d <<= 1) {
        float t = __shfl_up_sync(FULLM, S, d, 16);
        if (lane >= d) S += t;
    }
    float P111 = shf(S, 13);               // prefix over X[0..111]
    float slo = xlo;                       // inclusive scan -> prefix X[0..lane]
    #pragma unroll
    for (int d = 1; d < 16; d <<= 1) {
        float t = __shfl_up_sync(FULLM, slo, d, 16);
        if (lane >= d) slo += t;
    }
    float shi = xhi;                       // inclusive scan -> sum X[112..112+lane]
    #pragma unroll
    for (int d = 1; d < 16; d <<= 1) {
        float t = __shfl_up_sync(FULLM, shi, d, 16);
        if (lane >= d) shi += t;
    }
    float xs = P111 + shi - slo + xlo;     // sum_{j=lane}^{112+lane} X[j]

    // ---- remaining rows of G via lag recurrence (lane k holds column k) ----
    float g[16];
    float cur = g0;
    g[0] = cur;
    const float xk1 = shfu(xlo);           // X[k-1] (loop-invariant)
    #pragma unroll
    for (int l = 1; l < 16; l++) {
        float a   = shfu(cur);             // G[l-1][k-1]
        float xl1 = shf(xlo, l - 1);       // X[l-1]
        float xhl = shf(xhi, l);           // X[112+l]
        float nxt = fmaf(xhl, xhi, fmaf(-xl1, xk1, a));
        float bnd = shf(g0, l);            // G[l][0]
        nxt = (lane == 0) ? bnd : nxt;
        cur = nxt;
        g[l] = cur;
    }

    // ---- trace + diagonal loading ----
    float dd = g[0];
    #pragma unroll
    for (int j = 1; j < 16; j++) if (lane == j) dd = g[j];   // G[lane][lane]
    float tr = dd;
    tr += shfx(tr, 8); tr += shfx(tr, 4); tr += shfx(tr, 2); tr += shfx(tr, 1);
    float dload = (DLc / 16.0f) * tr;
    #pragma unroll
    for (int j = 0; j < 16; j++) g[j] += (lane == j) ? dload : 0.0f;

    // ---- Cholesky (row-distributed) + fused forward solve + transpose capture
    //      column broadcast through smem: STS + LDS.128 quads, double-buffered.
    float linv[16], ltr[16];
    #pragma unroll
    for (int j = 0; j < 16; j++) ltr[j] = 0.0f;
    float s = 0.0f, yown = 0.0f;
    #pragma unroll
    for (int k = 0; k < 16; k++) {
        float diag = shf(g[k], k);
        float inv = rsqrtf(diag);
        inv = inv * fmaf(-0.5f * diag * inv, inv, 1.5f);   // Newton refine
        float lik = g[k] * inv;        // lane i: L[i][k] (valid i>=k)
        linv[k] = inv;
        float t = (1.0f - s) * inv;    // meaningful on lane k
        float yk = shf(t, k);
        if (lane == k) yown = yk;
        s = fmaf(lik, yk, s);
        // publish column k, then read it back as broadcast quads
        scol[k & 1][grp][lane] = lik;
        __syncwarp();
        const float* col = scol[k & 1][grp];
        #pragma unroll
        for (int q = 0; q < 4; q++) {
            if (4 * q + 3 >= k + 1) {
                float4 cq = *(const float4*)(col + 4 * q);
                #pragma unroll
                for (int jj = 0; jj < 4; jj++) {
                    int j = 4 * q + jj;
                    if (j >= k + 1) {
                        float ljk = (jj == 0) ? cq.x : (jj == 1) ? cq.y
                                  : (jj == 2) ? cq.z : cq.w;
                        if (lane == k) ltr[j] = ljk;   // lane k: column k = L[j][k]
                        g[j] = fmaf(-lik, ljk, g[j]);
                    }
                }
            }
        }
    }

    // ---- backward solve L^T u = y: 1 shuffle per step ----
    float sacc = 0.0f, uown = 0.0f;
    #pragma unroll
    for (int j = 15; j >= 0; j--) {
        float t = (yown - sacc) * linv[j];   // meaningful on lane j
        float uj = shf(t, j);
        if (lane == j) uown = uj;
        sacc = fmaf(ltr[j], uj, sacc);
    }

    // ---- y = <u, xs> / (M * sum(u) + 1e-10) ----
    float dot = uown * xs;
    float sv  = uown;
    #pragma unroll
    for (int m = 8; m; m >>= 1) { dot += shfx(dot, m); sv += shfx(sv, m); }
    float y = dot / fmaf(113.0f, sv, 1e-10f);
    if (lane == 0) out[p] = y;
}

extern "C" void kernel_launch(void* const* d_in, const int* in_sizes, int n_in,
                              void* d_out, int out_size)
{
    const float* rf  = (const float*)d_in[0];
    const float* t0  = (const float*)d_in[1];
    const float* dtx = (const float*)d_in[2];
    const float* drx = (const float*)d_in[3];
    const float* fs  = (const float*)d_in[4];
    // d_in[5] = f0 (unused), d_in[7] = apod (unused, all-ones)
    const float* c0  = (const float*)d_in[6];
    prep_kernel<<<(Bn * Cn * NSn) / 256, 256>>>(rf);
    mvdr_kernel<<<PIX / PPB, TPB>>>(t0, dtx, drx, fs, c0, (float*)d_out);
}